// round 1
// baseline (speedup 1.0000x reference)
#include <cuda_runtime.h>
#include <cuda_bf16.h>
#include <cstdint>

// Problem constants (fixed shapes from reference)
#define NPROB 512            // B*S = 32*16
#define MDIM  128
#define NDIM  256
#define EPSF  1e-6f
#define MUF   0.01f
#define KITER 30
#define LMAX  25
#define MASK_ALL 0x01FFFFFFu // 25 bits

// Persistent device state (static __device__ arrays are the sanctioned scratch)
__device__ float    g_Aw[(size_t)NPROB * MDIM * NDIM]; // row-normalized A, 64MB
__device__ float    g_bw[NPROB * MDIM];
__device__ float    g_x[NPROB * NDIM];
__device__ float    g_grad[NPROB * NDIM];
__device__ unsigned g_mask[NPROB];
__device__ float    g_step;

__device__ __forceinline__ float warp_allreduce_add(float v) {
#pragma unroll
    for (int o = 16; o; o >>= 1) v += __shfl_xor_sync(0xffffffffu, v, o);
    return v;
}

__device__ __forceinline__ float dot8(float4 a0, float4 a1, float4 b0, float4 b1) {
    float s = a0.x * b0.x + a0.y * b0.y + a0.z * b0.z + a0.w * b0.w;
    s += a1.x * b1.x + a1.y * b1.y + a1.z * b1.z + a1.w * b1.w;
    return s;
}

// ---------------------------------------------------------------------------
// K0: per-problem setup. Row-normalize A -> g_Aw, b -> g_bw, deterministic
// interior init x = lower + t, feasibility repair, write g_x.
// 512 blocks x 256 threads (8 warps, 16 rows per warp; lane owns fixed n-quads).
// ---------------------------------------------------------------------------
__global__ void k0_setup(const float* __restrict__ xraw,
                         const float* __restrict__ Ain,
                         const float* __restrict__ bin,
                         const float* __restrict__ lowin) {
    const int p    = blockIdx.x;
    const int tid  = threadIdx.x;
    const int lane = tid & 31;
    const int w    = tid >> 5;

    __shared__ __align__(16) float s_bw[MDIM];
    __shared__ __align__(16) float s_Ad[MDIM];
    __shared__ __align__(16) float s_s[MDIM];
    __shared__ __align__(16) float s_x[NDIM];
    __shared__ __align__(16) float s_red[MDIM];
    __shared__ int s_feas;

    const float* A  = Ain   + (size_t)p * MDIM * NDIM;
    const float* lo = lowin + (size_t)p * NDIM;
    const float* bb = bin   + (size_t)p * MDIM;
    float*       Aw = g_Aw  + (size_t)p * MDIM * NDIM;

    if (tid == 0) s_feas = 1;

    const int n0 = 4 * lane;
    const int n1 = 128 + 4 * lane;
    const float4 l0 = *(const float4*)(lo + n0);
    const float4 l1 = *(const float4*)(lo + n1);

    // Pass over rows: norm, normalize+store Aw, Ad = Aw@1, sdot = Aw@lower
    for (int m = w; m < MDIM; m += 8) {
        const float4 a0 = *(const float4*)(A + (size_t)m * NDIM + n0);
        const float4 a1 = *(const float4*)(A + (size_t)m * NDIM + n1);
        float ss = dot8(a0, a1, a0, a1);
        ss = warp_allreduce_add(ss);
        const float norm = fmaxf(sqrtf(ss), 1e-12f);
        float4 w0, w1;
        w0.x = a0.x / norm; w0.y = a0.y / norm; w0.z = a0.z / norm; w0.w = a0.w / norm;
        w1.x = a1.x / norm; w1.y = a1.y / norm; w1.z = a1.z / norm; w1.w = a1.w / norm;
        *(float4*)(Aw + (size_t)m * NDIM + n0) = w0;
        *(float4*)(Aw + (size_t)m * NDIM + n1) = w1;
        float ad = (w0.x + w0.y + w0.z + w0.w) + (w1.x + w1.y + w1.z + w1.w);
        float sd = dot8(w0, w1, l0, l1);
        ad = warp_allreduce_add(ad);
        sd = warp_allreduce_add(sd);
        if (lane == 0) {
            const float bwm = bb[m] / norm;
            s_bw[m] = bwm;
            g_bw[p * MDIM + m] = bwm;
            s_Ad[m] = ad;
            s_s[m]  = bwm - sd;
        }
    }
    __syncthreads();

    // t = max(0.5 * min_m ratio, 2*eps)
    if (tid < MDIM) {
        const float ad = s_Ad[tid];
        s_red[tid] = (ad > 0.f) ? (s_s[tid] / fmaxf(ad, 1e-12f))
                                : __int_as_float(0x7f800000); // +inf
    }
    __syncthreads();
    for (int off = 64; off >= 1; off >>= 1) {
        if (tid < off) s_red[tid] = fminf(s_red[tid], s_red[tid + off]);
        __syncthreads();
    }
    const float t = fmaxf(0.5f * s_red[0], 2.f * EPSF);

    if (tid < NDIM) s_x[tid] = lo[tid] + t;
    __syncthreads();

    // Feasibility check: Ax <= bw - eps (fresh dot), x >= lower + eps
    float4 xq0, xq1;
    xq0.x = l0.x + t; xq0.y = l0.y + t; xq0.z = l0.z + t; xq0.w = l0.w + t;
    xq1.x = l1.x + t; xq1.y = l1.y + t; xq1.z = l1.z + t; xq1.w = l1.w + t;
    for (int m = w; m < MDIM; m += 8) {
        const float4 a0 = *(const float4*)(Aw + (size_t)m * NDIM + n0);
        const float4 a1 = *(const float4*)(Aw + (size_t)m * NDIM + n1);
        float d = dot8(a0, a1, xq0, xq1);
        d = warp_allreduce_add(d);
        if (lane == 0) {
            if (!(d <= s_bw[m] - EPSF)) atomicAnd(&s_feas, 0);
        }
    }
    if (tid < NDIM) {
        if (!(s_x[tid] >= lo[tid] + EPSF)) atomicAnd(&s_feas, 0);
    }
    __syncthreads();

    if (tid < NDIM) {
        float xv = s_x[tid];
        if (!s_feas) xv = 0.5f * (fmaxf(xv, 0.f) + lo[tid]);
        g_x[(size_t)p * NDIM + tid] = xv;
    }
}

// ---------------------------------------------------------------------------
// K1: one iteration body for problem p.
//   prologue (k>0): x -= step_{k-1} * grad_{k-1}
//   pass1 (fused):  Ax_m = A_m . x ; v_m = mu/max(bw-Ax,1e-12); gbar += A_m * v_m
//   grad, column feasibility bits
//   pass2: Ag_m = A_m . grad ; row feasibility bits (Axc = Ax - s*Ag)
//   write 25-bit mask
// 512 blocks x 256 threads.
// ---------------------------------------------------------------------------
__global__ void k1_iter(int k,
                        const float* __restrict__ xraw,
                        const float* __restrict__ lowin) {
    const int p    = blockIdx.x;
    const int tid  = threadIdx.x;
    const int lane = tid & 31;
    const int w    = tid >> 5;

    __shared__ __align__(16) float s_x[NDIM];
    __shared__ __align__(16) float s_grad[NDIM];
    __shared__ __align__(16) float s_bw[MDIM];
    __shared__ __align__(16) float s_Ax[MDIM];
    __shared__ __align__(16) float s_gb[8 * NDIM]; // per-warp gbar partials
    __shared__ unsigned s_mask;

    const float* Aw = g_Aw  + (size_t)p * MDIM * NDIM;
    const float* lo = lowin + (size_t)p * NDIM;
    const float* xr = xraw  + (size_t)p * NDIM;
    float*       xg = g_x   + (size_t)p * NDIM;
    float*       gg = g_grad+ (size_t)p * NDIM;

    if (tid == 0) s_mask = MASK_ALL;

    // prologue: apply previous iteration's globally-chosen step
    if (tid < NDIM) {
        float xv = xg[tid];
        if (k > 0) {
            const float st = g_step;           // 0.0 when no step accepted
            xv = fmaf(-st, gg[tid], xv);
            xg[tid] = xv;
        }
        s_x[tid] = xv;
    }
    if (tid < MDIM) s_bw[tid] = g_bw[p * MDIM + tid];
    __syncthreads();

    const int n0 = 4 * lane;
    const int n1 = 128 + 4 * lane;
    const float4 xq0 = *(const float4*)(s_x + n0);
    const float4 xq1 = *(const float4*)(s_x + n1);

    float4 ga0 = make_float4(0.f, 0.f, 0.f, 0.f);
    float4 ga1 = make_float4(0.f, 0.f, 0.f, 0.f);

    // pass 1: fused Ax + A^T v accumulation
#pragma unroll 4
    for (int m = w; m < MDIM; m += 8) {
        const float4 a0 = *(const float4*)(Aw + (size_t)m * NDIM + n0);
        const float4 a1 = *(const float4*)(Aw + (size_t)m * NDIM + n1);
        float d = dot8(a0, a1, xq0, xq1);
        d = warp_allreduce_add(d);
        const float bwm = s_bw[m];
        const float v = MUF / fmaxf(bwm - d, 1e-12f);
        if (lane == 0) s_Ax[m] = d;
        ga0.x = fmaf(a0.x, v, ga0.x); ga0.y = fmaf(a0.y, v, ga0.y);
        ga0.z = fmaf(a0.z, v, ga0.z); ga0.w = fmaf(a0.w, v, ga0.w);
        ga1.x = fmaf(a1.x, v, ga1.x); ga1.y = fmaf(a1.y, v, ga1.y);
        ga1.z = fmaf(a1.z, v, ga1.z); ga1.w = fmaf(a1.w, v, ga1.w);
    }
    *(float4*)(s_gb + w * NDIM + n0) = ga0;
    *(float4*)(s_gb + w * NDIM + n1) = ga1;
    __syncthreads();

    // grad + column-constraint mask bits
    if (tid < NDIM) {
        float gb = 0.f;
#pragma unroll
        for (int j = 0; j < 8; j++) gb += s_gb[j * NDIM + tid];
        const float xv  = s_x[tid];
        const float lov = lo[tid];
        const float slo = fmaxf(xv - lov, 1e-12f);
        const float gr  = (xv - xr[tid]) + gb + MUF / slo;
        s_grad[tid] = gr;
        gg[tid]     = gr;

        const float lim = lov + EPSF;
        unsigned mk = MASK_ALL;
        float st = 1.f;
#pragma unroll
        for (int l = 0; l < LMAX; l++) {
            const float c = fmaf(-st, gr, xv);
            if (!(c >= lim)) mk &= ~(1u << l);
            st *= 0.5f;
        }
        atomicAnd(&s_mask, mk);
    }
    __syncthreads();

    // pass 2: Ag + row-constraint mask bits
    const float4 gq0 = *(const float4*)(s_grad + n0);
    const float4 gq1 = *(const float4*)(s_grad + n1);
    unsigned wmask = MASK_ALL;
#pragma unroll 4
    for (int m = w; m < MDIM; m += 8) {
        const float4 a0 = *(const float4*)(Aw + (size_t)m * NDIM + n0);
        const float4 a1 = *(const float4*)(Aw + (size_t)m * NDIM + n1);
        float ag = dot8(a0, a1, gq0, gq1);
        ag = warp_allreduce_add(ag);
        const float ax  = s_Ax[m];
        const float lim = s_bw[m] - EPSF;
        float st = 1.f;
#pragma unroll
        for (int l = 0; l < LMAX; l++) {
            const float axc = fmaf(-st, ag, ax);
            if (!(axc <= lim)) wmask &= ~(1u << l);
            st *= 0.5f;
        }
    }
    if (lane == 0) atomicAnd(&s_mask, wmask);
    __syncthreads();
    if (tid == 0) g_mask[p] = s_mask;
}

// ---------------------------------------------------------------------------
// K2: global line-search decision. AND of 512 masks, first accepted step =
// lowest set bit (steps are decreasing powers of two). step=0 if none.
// ---------------------------------------------------------------------------
__global__ void k2_reduce() {
    const int tid = threadIdx.x; // 512 threads
    __shared__ unsigned sm[16];
    unsigned v = g_mask[tid];
    v = __reduce_and_sync(0xffffffffu, v);
    if ((tid & 31) == 0) sm[tid >> 5] = v;
    __syncthreads();
    if (tid == 0) {
        unsigned t = 0xffffffffu;
#pragma unroll
        for (int i = 0; i < 16; i++) t &= sm[i];
        t &= MASK_ALL;
        float st = 0.f;
        if (t) {
            const int idx = __ffs(t) - 1;
            st = ldexpf(1.f, -idx);
        }
        g_step = st;
    }
}

// ---------------------------------------------------------------------------
// K3: apply final (iteration 29) step and ReLU into d_out.
// ---------------------------------------------------------------------------
__global__ void k3_finalize(float* __restrict__ out) {
    const int i = blockIdx.x * blockDim.x + threadIdx.x;
    if (i < NPROB * NDIM) {
        const float st = g_step;
        const float xv = fmaf(-st, g_grad[i], g_x[i]);
        out[i] = fmaxf(xv, 0.f);
    }
}

extern "C" void kernel_launch(void* const* d_in, const int* in_sizes, int n_in,
                              void* d_out, int out_size) {
    // Identify inputs by size (dict order: x_raw, A, b, lower).
    int iA = 1, ib = 2, iv1 = 0, iv2 = 3;
    {
        int big = -1, small = -1, v1 = -1, v2 = -1;
        for (int i = 0; i < n_in; i++) {
            if (in_sizes[i] == NPROB * MDIM * NDIM) big = i;
            else if (in_sizes[i] == NPROB * MDIM)   small = i;
            else if (v1 < 0) v1 = i;
            else             v2 = i;
        }
        if (big >= 0 && small >= 0 && v1 >= 0 && v2 >= 0) {
            iA = big; ib = small; iv1 = v1; iv2 = v2;
        }
    }
    const float* xraw = (const float*)d_in[iv1];
    const float* A    = (const float*)d_in[iA];
    const float* b    = (const float*)d_in[ib];
    const float* low  = (const float*)d_in[iv2];
    float* out = (float*)d_out;

    k0_setup<<<NPROB, 256>>>(xraw, A, b, low);
    for (int k = 0; k < KITER; k++) {
        k1_iter<<<NPROB, 256>>>(k, xraw, low);
        k2_reduce<<<1, 512>>>();
    }
    k3_finalize<<<(NPROB * NDIM + 255) / 256, 256>>>(out);
}

// round 2
// speedup vs baseline: 1.4908x; 1.4908x over previous
#include <cuda_runtime.h>
#include <cstdint>

#define NPROB 512            // B*S = 32*16
#define MDIM  128
#define NDIM  256
#define EPSF  1e-6f
#define MUF   0.01f
#define KITER 30
#define LMAX  25
#define MASK_ALL 0x01FFFFFFu // 25 bits
#define TPB   256

// Persistent device state
__device__ float    g_Aw[(size_t)NPROB * MDIM * NDIM]; // row-normalized A (64MB)
__device__ unsigned g_and[KITER];                       // global AND of masks per iter
__device__ unsigned g_count;                            // barrier arrival counter (stays 0)
__device__ unsigned g_sense;                            // barrier sense (alternates)

__device__ __forceinline__ float warp_allreduce_add(float v) {
#pragma unroll
    for (int o = 16; o; o >>= 1) v += __shfl_xor_sync(0xffffffffu, v, o);
    return v;
}

__device__ __forceinline__ float dot8(float4 a0, float4 a1, float4 b0, float4 b1) {
    float s = a0.x * b0.x + a0.y * b0.y + a0.z * b0.z + a0.w * b0.w;
    s += a1.x * b1.x + a1.y * b1.y + a1.z * b1.z + a1.w * b1.w;
    return s;
}

// Grid-wide sense-reversal barrier. All NPROB CTAs are co-resident
// (guaranteed by __launch_bounds__(256,4): 4 CTAs/SM * 148 SMs = 592 >= 512).
#define GRID_BARRIER()                                                        \
    do {                                                                      \
        __syncthreads();                                                      \
        if (tid == 0) {                                                       \
            const unsigned target = sense ^ 1u;                               \
            __threadfence();                                                  \
            if (atomicAdd(&g_count, 1u) == NPROB - 1u) {                      \
                atomicExch(&g_count, 0u);                                     \
                __threadfence();                                              \
                atomicExch(&g_sense, target);                                 \
            } else {                                                          \
                while (*(volatile unsigned*)&g_sense != target)               \
                    __nanosleep(64);                                          \
            }                                                                 \
            sense = target;                                                   \
            __threadfence();                                                  \
        }                                                                     \
        __syncthreads();                                                      \
    } while (0)

__global__ void __launch_bounds__(TPB, 4)
persist_kernel(const float* __restrict__ xraw,
               const float* __restrict__ Ain,
               const float* __restrict__ bin,
               const float* __restrict__ lowin,
               float* __restrict__ out)
{
    const int p    = blockIdx.x;
    const int tid  = threadIdx.x;
    const int lane = tid & 31;
    const int w    = tid >> 5;

    __shared__ __align__(16) float s_x[NDIM];
    __shared__ __align__(16) float s_grad[NDIM];
    __shared__ __align__(16) float s_lo[NDIM];
    __shared__ __align__(16) float s_xr[NDIM];
    __shared__ __align__(16) float s_bw[MDIM];
    __shared__ __align__(16) float s_Ax[MDIM];
    __shared__ __align__(16) float s_red[MDIM];
    __shared__ __align__(16) float s_gb[8 * NDIM];   // per-warp gbar partials
    __shared__ unsigned s_mask;
    __shared__ float    s_step;
    __shared__ int      s_feas;

    const float* A  = Ain  + (size_t)p * MDIM * NDIM;
    float*       Aw = g_Aw + (size_t)p * MDIM * NDIM;

    // Read sense BEFORE first arrive (all CTAs read pre-flip value).
    unsigned sense = *(volatile unsigned*)&g_sense;

    // Reset global AND words for this run (covered by barrier #0).
    if (p == 0 && tid < KITER) g_and[tid] = MASK_ALL;

    if (tid < NDIM) {
        s_lo[tid] = lowin[p * NDIM + tid];
        s_xr[tid] = xraw[p * NDIM + tid];
    }
    if (tid == 0) s_feas = 1;
    __syncthreads();

    const int n0 = 4 * lane;
    const int n1 = 128 + 4 * lane;
    const float4 l0 = *(const float4*)(s_lo + n0);
    const float4 l1 = *(const float4*)(s_lo + n1);

    // ---------------- setup: row-normalize, Ad = Aw@1, slack at lower --------
    for (int m = w; m < MDIM; m += 8) {
        const float4 a0 = *(const float4*)(A + (size_t)m * NDIM + n0);
        const float4 a1 = *(const float4*)(A + (size_t)m * NDIM + n1);
        float ss = warp_allreduce_add(dot8(a0, a1, a0, a1));
        const float norm = fmaxf(sqrtf(ss), 1e-12f);
        float4 w0, w1;
        w0.x = a0.x / norm; w0.y = a0.y / norm; w0.z = a0.z / norm; w0.w = a0.w / norm;
        w1.x = a1.x / norm; w1.y = a1.y / norm; w1.z = a1.z / norm; w1.w = a1.w / norm;
        *(float4*)(Aw + (size_t)m * NDIM + n0) = w0;
        *(float4*)(Aw + (size_t)m * NDIM + n1) = w1;
        float ad = (w0.x + w0.y + w0.z + w0.w) + (w1.x + w1.y + w1.z + w1.w);
        float sd = dot8(w0, w1, l0, l1);
        ad = warp_allreduce_add(ad);
        sd = warp_allreduce_add(sd);
        if (lane == 0) {
            const float bwm = bin[p * MDIM + m] / norm;
            s_bw[m]  = bwm;
            s_Ax[m]  = ad;          // temp: Ad
            s_red[m] = bwm - sd;    // temp: slack at lower
        }
    }
    __syncthreads();

    // t = max(0.5 * min_m ratio, 2*eps)
    if (tid < MDIM) {
        const float ad = s_Ax[tid];
        s_red[tid] = (ad > 0.f) ? (s_red[tid] / fmaxf(ad, 1e-12f))
                                : __int_as_float(0x7f800000); // +inf
    }
    __syncthreads();
    for (int off = 64; off >= 1; off >>= 1) {
        if (tid < off) s_red[tid] = fminf(s_red[tid], s_red[tid + off]);
        __syncthreads();
    }
    const float t = fmaxf(0.5f * s_red[0], 2.f * EPSF);

    // feasibility of x = lower + t (fresh dots, matching reference)
    {
        float4 xq0, xq1;
        xq0.x = l0.x + t; xq0.y = l0.y + t; xq0.z = l0.z + t; xq0.w = l0.w + t;
        xq1.x = l1.x + t; xq1.y = l1.y + t; xq1.z = l1.z + t; xq1.w = l1.w + t;
        for (int m = w; m < MDIM; m += 8) {
            const float4 a0 = *(const float4*)(Aw + (size_t)m * NDIM + n0);
            const float4 a1 = *(const float4*)(Aw + (size_t)m * NDIM + n1);
            float d = warp_allreduce_add(dot8(a0, a1, xq0, xq1));
            if (lane == 0) {
                if (!(d <= s_bw[m] - EPSF)) atomicAnd(&s_feas, 0);
            }
        }
        if (tid < NDIM) {
            const float xv = s_lo[tid] + t;
            if (!(xv >= s_lo[tid] + EPSF)) atomicAnd(&s_feas, 0);
        }
        __syncthreads();
        if (tid < NDIM) {
            float xv = s_lo[tid] + t;
            if (!s_feas) xv = 0.5f * (fmaxf(xv, 0.f) + s_lo[tid]);
            s_x[tid] = xv;
        }
    }

    GRID_BARRIER();   // barrier #0: g_and init + everyone's setup done

    // ---------------- main loop: 30 iterations, fully fused ------------------
    for (int k = 0; k < KITER; k++) {
        if (tid == 0) s_mask = MASK_ALL;
        __syncthreads();

        const float4 xq0 = *(const float4*)(s_x + n0);
        const float4 xq1 = *(const float4*)(s_x + n1);

        // pass 1: fused Ax + A^T v accumulation
        float4 ga0 = make_float4(0.f, 0.f, 0.f, 0.f);
        float4 ga1 = make_float4(0.f, 0.f, 0.f, 0.f);
#pragma unroll 4
        for (int m = w; m < MDIM; m += 8) {
            const float4 a0 = *(const float4*)(Aw + (size_t)m * NDIM + n0);
            const float4 a1 = *(const float4*)(Aw + (size_t)m * NDIM + n1);
            float d = warp_allreduce_add(dot8(a0, a1, xq0, xq1));
            const float v = MUF / fmaxf(s_bw[m] - d, 1e-12f);
            if (lane == 0) s_Ax[m] = d;
            ga0.x = fmaf(a0.x, v, ga0.x); ga0.y = fmaf(a0.y, v, ga0.y);
            ga0.z = fmaf(a0.z, v, ga0.z); ga0.w = fmaf(a0.w, v, ga0.w);
            ga1.x = fmaf(a1.x, v, ga1.x); ga1.y = fmaf(a1.y, v, ga1.y);
            ga1.z = fmaf(a1.z, v, ga1.z); ga1.w = fmaf(a1.w, v, ga1.w);
        }
        *(float4*)(s_gb + w * NDIM + n0) = ga0;
        *(float4*)(s_gb + w * NDIM + n1) = ga1;
        __syncthreads();

        // grad + column-constraint mask bits
        if (tid < NDIM) {
            float gb = 0.f;
#pragma unroll
            for (int j = 0; j < 8; j++) gb += s_gb[j * NDIM + tid];
            const float xv  = s_x[tid];
            const float lov = s_lo[tid];
            const float slo = fmaxf(xv - lov, 1e-12f);
            const float gr  = (xv - s_xr[tid]) + gb + MUF / slo;
            s_grad[tid] = gr;

            const float lim = lov + EPSF;
            // fast path: gr<=0 && xv>=lim  ==>  c = xv - s*gr >= xv >= lim for all s
            if (!(gr <= 0.f && xv >= lim)) {
                unsigned mk = MASK_ALL;
                float st = 1.f;
#pragma unroll
                for (int l = 0; l < LMAX; l++) {
                    const float c = fmaf(-st, gr, xv);
                    if (!(c >= lim)) mk &= ~(1u << l);
                    st *= 0.5f;
                }
                if (mk != MASK_ALL) atomicAnd(&s_mask, mk);
            }
        }
        __syncthreads();

        // pass 2: Ag + row-constraint mask bits
        const float4 gq0 = *(const float4*)(s_grad + n0);
        const float4 gq1 = *(const float4*)(s_grad + n1);
        unsigned wmask = MASK_ALL;
#pragma unroll 4
        for (int m = w; m < MDIM; m += 8) {
            const float4 a0 = *(const float4*)(Aw + (size_t)m * NDIM + n0);
            const float4 a1 = *(const float4*)(Aw + (size_t)m * NDIM + n1);
            float ag = warp_allreduce_add(dot8(a0, a1, gq0, gq1));
            const float ax  = s_Ax[m];
            const float lim = s_bw[m] - EPSF;
            // fast path (uniform across warp): ag>=0 && ax<=lim
            //   ==> axc = ax - s*ag <= ax <= lim for all s (monotone rounding)
            if (!(ag >= 0.f && ax <= lim)) {
                float st = 1.f;
#pragma unroll
                for (int l = 0; l < LMAX; l++) {
                    const float axc = fmaf(-st, ag, ax);
                    if (!(axc <= lim)) wmask &= ~(1u << l);
                    st *= 0.5f;
                }
            }
        }
        if (lane == 0 && wmask != MASK_ALL) atomicAnd(&s_mask, wmask);
        __syncthreads();

        if (tid == 0) atomicAnd(&g_and[k], s_mask);

        GRID_BARRIER();   // all masks for iteration k combined

        if (tid == 0) {
            const unsigned tt = *(volatile unsigned*)&g_and[k] & MASK_ALL;
            float st = 0.f;
            if (tt) st = ldexpf(1.f, -(__ffs(tt) - 1));
            s_step = st;
        }
        __syncthreads();

        if (tid < NDIM) s_x[tid] = fmaf(-s_step, s_grad[tid], s_x[tid]);
        // next iteration's leading __syncthreads covers visibility of s_x
    }

    // finalize: relu(x) -> out (each tid owns its element; no sync needed)
    if (tid < NDIM) out[p * NDIM + tid] = fmaxf(s_x[tid], 0.f);
}

extern "C" void kernel_launch(void* const* d_in, const int* in_sizes, int n_in,
                              void* d_out, int out_size) {
    // Identify inputs by size (dict order: x_raw, A, b, lower).
    int iA = 1, ib = 2, iv1 = 0, iv2 = 3;
    {
        int big = -1, small = -1, v1 = -1, v2 = -1;
        for (int i = 0; i < n_in; i++) {
            if (in_sizes[i] == NPROB * MDIM * NDIM) big = i;
            else if (in_sizes[i] == NPROB * MDIM)   small = i;
            else if (v1 < 0) v1 = i;
            else             v2 = i;
        }
        if (big >= 0 && small >= 0 && v1 >= 0 && v2 >= 0) {
            iA = big; ib = small; iv1 = v1; iv2 = v2;
        }
    }
    const float* xr  = (const float*)d_in[iv1];
    const float* A   = (const float*)d_in[iA];
    const float* b   = (const float*)d_in[ib];
    const float* low = (const float*)d_in[iv2];
    float* out = (float*)d_out;

    persist_kernel<<<NPROB, TPB>>>(xr, A, b, low, out);
}

// round 4
// speedup vs baseline: 1.5705x; 1.0534x over previous
#include <cuda_runtime.h>
#include <cstdint>

#define NPROB 512            // B*S = 32*16
#define MDIM  128
#define NDIM  256
#define EPSF  1e-6f
#define MUF   0.01f
#define KITER 30
#define LMAX  25
#define MASK_ALL 0x01FFFFFFu // 25 bits
#define TPB   256
#define CJ    5              // cached row-groups per warp (rows 0..39 in smem)
#define CROWS (CJ * 8)       // 40 rows cached
#define DYNSMEM (CROWS * NDIM * 4)

// Persistent device state
__device__ float    g_Aw[(size_t)NPROB * MDIM * NDIM]; // row-normalized A (64MB)
__device__ unsigned g_and[KITER];                       // global AND of masks per iter
__device__ unsigned g_count;                            // barrier arrival counter
__device__ unsigned g_sense;                            // barrier sense

__device__ __forceinline__ float warp_allreduce_add(float v) {
#pragma unroll
    for (int o = 16; o; o >>= 1) v += __shfl_xor_sync(0xffffffffu, v, o);
    return v;
}

__device__ __forceinline__ float dot8(float4 a0, float4 a1, float4 b0, float4 b1) {
    float s = a0.x * b0.x + a0.y * b0.y + a0.z * b0.z + a0.w * b0.w;
    s += a1.x * b1.x + a1.y * b1.y + a1.z * b1.z + a1.w * b1.w;
    return s;
}

// Grid-wide sense-reversal barrier. All NPROB CTAs co-resident:
// __launch_bounds__(256,4) + ~54KB smem/CTA -> 4 CTAs/SM * 148 = 592 >= 512.
#define GRID_BARRIER()                                                        \
    do {                                                                      \
        __syncthreads();                                                      \
        if (tid == 0) {                                                       \
            const unsigned target = sense ^ 1u;                               \
            __threadfence();                                                  \
            if (atomicAdd(&g_count, 1u) == NPROB - 1u) {                      \
                atomicExch(&g_count, 0u);                                     \
                __threadfence();                                              \
                atomicExch(&g_sense, target);                                 \
            } else {                                                          \
                while (*(volatile unsigned*)&g_sense != target)               \
                    __nanosleep(64);                                          \
            }                                                                 \
            sense = target;                                                   \
            __threadfence();                                                  \
        }                                                                     \
        __syncthreads();                                                      \
    } while (0)

__global__ void __launch_bounds__(TPB, 4)
persist_kernel(const float* __restrict__ xraw,
               const float* __restrict__ Ain,
               const float* __restrict__ bin,
               const float* __restrict__ lowin,
               float* __restrict__ out)
{
    extern __shared__ __align__(16) float sA[];   // CROWS x NDIM pinned A rows

    const int p    = blockIdx.x;
    const int tid  = threadIdx.x;
    const int lane = tid & 31;
    const int w    = tid >> 5;

    __shared__ __align__(16) float s_x[NDIM];
    __shared__ __align__(16) float s_grad[NDIM];
    __shared__ __align__(16) float s_lo[NDIM];
    __shared__ __align__(16) float s_xr[NDIM];
    __shared__ __align__(16) float s_bw[MDIM];
    __shared__ __align__(16) float s_Ax[MDIM];
    __shared__ __align__(16) float s_gb[8 * NDIM];   // per-warp gbar partials
    __shared__ unsigned s_mask;
    __shared__ float    s_step;
    __shared__ int      s_feas;

    const float* A  = Ain  + (size_t)p * MDIM * NDIM;
    float*       Aw = g_Aw + (size_t)p * MDIM * NDIM;

    // Read sense BEFORE first arrive (all CTAs read pre-flip value).
    unsigned sense = *(volatile unsigned*)&g_sense;

    if (p == 0 && tid < KITER) g_and[tid] = MASK_ALL;

    if (tid < NDIM) {
        s_lo[tid] = lowin[p * NDIM + tid];
        s_xr[tid] = xraw[p * NDIM + tid];
    }
    if (tid == 0) s_feas = 1;
    __syncthreads();

    const int n0 = 4 * lane;
    const int n1 = 128 + 4 * lane;
    const float4 l0 = *(const float4*)(s_lo + n0);
    const float4 l1 = *(const float4*)(s_lo + n1);

    float* s_red = s_gb;   // alias: s_gb unused during setup

    // ---------------- setup: row-normalize, cache first 40 rows in smem -----
#pragma unroll 4
    for (int j = 0; j < 16; j++) {
        const int m = w + 8 * j;
        const float4 a0 = *(const float4*)(A + (size_t)m * NDIM + n0);
        const float4 a1 = *(const float4*)(A + (size_t)m * NDIM + n1);
        float ss = warp_allreduce_add(dot8(a0, a1, a0, a1));
        const float norm = fmaxf(sqrtf(ss), 1e-12f);
        float4 w0, w1;
        w0.x = a0.x / norm; w0.y = a0.y / norm; w0.z = a0.z / norm; w0.w = a0.w / norm;
        w1.x = a1.x / norm; w1.y = a1.y / norm; w1.z = a1.z / norm; w1.w = a1.w / norm;
        *(float4*)(Aw + (size_t)m * NDIM + n0) = w0;
        *(float4*)(Aw + (size_t)m * NDIM + n1) = w1;
        if (m < CROWS) {
            *(float4*)(sA + m * NDIM + n0) = w0;
            *(float4*)(sA + m * NDIM + n1) = w1;
        }
        float ad = (w0.x + w0.y + w0.z + w0.w) + (w1.x + w1.y + w1.z + w1.w);
        float sd = dot8(w0, w1, l0, l1);
        ad = warp_allreduce_add(ad);
        sd = warp_allreduce_add(sd);
        if (lane == 0) {
            const float bwm = bin[p * MDIM + m] / norm;
            s_bw[m]  = bwm;
            s_Ax[m]  = ad;          // temp: Ad
            s_red[m] = bwm - sd;    // temp: slack at lower
        }
    }
    __syncthreads();

    // t = max(0.5 * min_m ratio, 2*eps)
    if (tid < MDIM) {
        const float ad = s_Ax[tid];
        s_red[tid] = (ad > 0.f) ? (s_red[tid] / fmaxf(ad, 1e-12f))
                                : __int_as_float(0x7f800000); // +inf
    }
    __syncthreads();
    for (int off = 64; off >= 1; off >>= 1) {
        if (tid < off) s_red[tid] = fminf(s_red[tid], s_red[tid + off]);
        __syncthreads();
    }
    const float t = fmaxf(0.5f * s_red[0], 2.f * EPSF);
    __syncthreads();   // s_red (=s_gb) free again

    // feasibility of x = lower + t (fresh dots)
    {
        float4 xq0, xq1;
        xq0.x = l0.x + t; xq0.y = l0.y + t; xq0.z = l0.z + t; xq0.w = l0.w + t;
        xq1.x = l1.x + t; xq1.y = l1.y + t; xq1.z = l1.z + t; xq1.w = l1.w + t;
#pragma unroll
        for (int j = 0; j < CJ; j++) {
            const int m = w + 8 * j;
            const float4 a0 = *(const float4*)(sA + m * NDIM + n0);
            const float4 a1 = *(const float4*)(sA + m * NDIM + n1);
            float d = warp_allreduce_add(dot8(a0, a1, xq0, xq1));
            if (lane == 0 && !(d <= s_bw[m] - EPSF)) atomicAnd(&s_feas, 0);
        }
#pragma unroll 4
        for (int j = CJ; j < 16; j++) {
            const int m = w + 8 * j;
            const float4 a0 = *(const float4*)(Aw + (size_t)m * NDIM + n0);
            const float4 a1 = *(const float4*)(Aw + (size_t)m * NDIM + n1);
            float d = warp_allreduce_add(dot8(a0, a1, xq0, xq1));
            if (lane == 0 && !(d <= s_bw[m] - EPSF)) atomicAnd(&s_feas, 0);
        }
        if (tid < NDIM) {
            const float xv = s_lo[tid] + t;
            if (!(xv >= s_lo[tid] + EPSF)) atomicAnd(&s_feas, 0);
        }
        __syncthreads();
        if (tid < NDIM) {
            float xv = s_lo[tid] + t;
            if (!s_feas) xv = 0.5f * (fmaxf(xv, 0.f) + s_lo[tid]);
            s_x[tid] = xv;
        }
    }

    GRID_BARRIER();   // barrier #0: g_and init + everyone's setup done

    // ---------------- main loop ---------------------------------------------
    for (int k = 0; k < KITER; k++) {
        if (tid == 0) s_mask = MASK_ALL;
        __syncthreads();

        const float4 xq0 = *(const float4*)(s_x + n0);
        const float4 xq1 = *(const float4*)(s_x + n1);

        float4 ga0 = make_float4(0.f, 0.f, 0.f, 0.f);
        float4 ga1 = make_float4(0.f, 0.f, 0.f, 0.f);

        // pass 1 row body: d = A_m.x ; v = mu/slack ; gbar += A_m * v
#define P1_ROW(a0, a1, m)                                                     \
        do {                                                                  \
            float d = warp_allreduce_add(dot8(a0, a1, xq0, xq1));             \
            const float v = MUF / fmaxf(s_bw[m] - d, 1e-12f);                 \
            if (lane == 0) s_Ax[m] = d;                                       \
            ga0.x = fmaf((a0).x, v, ga0.x); ga0.y = fmaf((a0).y, v, ga0.y);   \
            ga0.z = fmaf((a0).z, v, ga0.z); ga0.w = fmaf((a0).w, v, ga0.w);   \
            ga1.x = fmaf((a1).x, v, ga1.x); ga1.y = fmaf((a1).y, v, ga1.y);   \
            ga1.z = fmaf((a1).z, v, ga1.z); ga1.w = fmaf((a1).w, v, ga1.w);   \
        } while (0)

        // gmem rows ascending (j=CJ..15): j=CJ was read last by prev pass 2
#pragma unroll 4
        for (int j = CJ; j < 16; j++) {
            const int m = w + 8 * j;
            const float4 a0 = *(const float4*)(Aw + (size_t)m * NDIM + n0);
            const float4 a1 = *(const float4*)(Aw + (size_t)m * NDIM + n1);
            P1_ROW(a0, a1, m);
        }
        // smem-pinned rows
#pragma unroll
        for (int j = 0; j < CJ; j++) {
            const int m = w + 8 * j;
            const float4 a0 = *(const float4*)(sA + m * NDIM + n0);
            const float4 a1 = *(const float4*)(sA + m * NDIM + n1);
            P1_ROW(a0, a1, m);
        }
#undef P1_ROW

        *(float4*)(s_gb + w * NDIM + n0) = ga0;
        *(float4*)(s_gb + w * NDIM + n1) = ga1;
        __syncthreads();

        // grad + column-constraint mask bits
        if (tid < NDIM) {
            float gb = 0.f;
#pragma unroll
            for (int j = 0; j < 8; j++) gb += s_gb[j * NDIM + tid];
            const float xv  = s_x[tid];
            const float lov = s_lo[tid];
            const float slo = fmaxf(xv - lov, 1e-12f);
            const float gr  = (xv - s_xr[tid]) + gb + MUF / slo;
            s_grad[tid] = gr;

            const float lim = lov + EPSF;
            if (!(gr <= 0.f && xv >= lim)) {   // fast path: all candidates pass
                unsigned mk = MASK_ALL;
                float st = 1.f;
#pragma unroll
                for (int l = 0; l < LMAX; l++) {
                    const float c = fmaf(-st, gr, xv);
                    if (!(c >= lim)) mk &= ~(1u << l);
                    st *= 0.5f;
                }
                if (mk != MASK_ALL) atomicAnd(&s_mask, mk);
            }
        }
        __syncthreads();

        // pass 2: Ag + row-constraint mask bits
        const float4 gq0 = *(const float4*)(s_grad + n0);
        const float4 gq1 = *(const float4*)(s_grad + n1);
        unsigned wmask = MASK_ALL;

#define P2_ROW(a0, a1, m)                                                     \
        do {                                                                  \
            float ag = warp_allreduce_add(dot8(a0, a1, gq0, gq1));            \
            const float ax  = s_Ax[m];                                        \
            const float lim = s_bw[m] - EPSF;                                 \
            if (!(ag >= 0.f && ax <= lim)) {                                  \
                float st = 1.f;                                               \
                _Pragma("unroll")                                             \
                for (int l = 0; l < LMAX; l++) {                              \
                    const float axc = fmaf(-st, ag, ax);                      \
                    if (!(axc <= lim)) wmask &= ~(1u << l);                   \
                    st *= 0.5f;                                               \
                }                                                             \
            }                                                                 \
        } while (0)

        // gmem rows DESCENDING (j=15..CJ): j=15 just read by pass 1 -> L1 hot
#pragma unroll 4
        for (int j = 15; j >= CJ; j--) {
            const int m = w + 8 * j;
            const float4 a0 = *(const float4*)(Aw + (size_t)m * NDIM + n0);
            const float4 a1 = *(const float4*)(Aw + (size_t)m * NDIM + n1);
            P2_ROW(a0, a1, m);
        }
        // smem-pinned rows
#pragma unroll
        for (int j = 0; j < CJ; j++) {
            const int m = w + 8 * j;
            const float4 a0 = *(const float4*)(sA + m * NDIM + n0);
            const float4 a1 = *(const float4*)(sA + m * NDIM + n1);
            P2_ROW(a0, a1, m);
        }
#undef P2_ROW

        if (lane == 0 && wmask != MASK_ALL) atomicAnd(&s_mask, wmask);
        __syncthreads();

        if (tid == 0) atomicAnd(&g_and[k], s_mask);

        GRID_BARRIER();   // all masks for iteration k combined

        if (tid == 0) {
            const unsigned tt = *(volatile unsigned*)&g_and[k] & MASK_ALL;
            float st = 0.f;
            if (tt) st = ldexpf(1.f, -(__ffs(tt) - 1));
            s_step = st;
        }
        __syncthreads();

        if (tid < NDIM) s_x[tid] = fmaf(-s_step, s_grad[tid], s_x[tid]);
        // next iteration's leading __syncthreads covers visibility of s_x
    }

    // finalize: relu(x) -> out
    if (tid < NDIM) out[p * NDIM + tid] = fmaxf(s_x[tid], 0.f);
}

extern "C" void kernel_launch(void* const* d_in, const int* in_sizes, int n_in,
                              void* d_out, int out_size) {
    // Identify inputs by size (dict order: x_raw, A, b, lower).
    int iA = 1, ib = 2, iv1 = 0, iv2 = 3;
    {
        int big = -1, small = -1, v1 = -1, v2 = -1;
        for (int i = 0; i < n_in; i++) {
            if (in_sizes[i] == NPROB * MDIM * NDIM) big = i;
            else if (in_sizes[i] == NPROB * MDIM)   small = i;
            else if (v1 < 0) v1 = i;
            else             v2 = i;
        }
        if (big >= 0 && small >= 0 && v1 >= 0 && v2 >= 0) {
            iA = big; ib = small; iv1 = v1; iv2 = v2;
        }
    }
    const float* xr  = (const float*)d_in[iv1];
    const float* A   = (const float*)d_in[iA];
    const float* b   = (const float*)d_in[ib];
    const float* low = (const float*)d_in[iv2];
    float* out = (float*)d_out;

    // Opt-in: static (~13.4KB) + dynamic (40KB) > 48KB default per-block limit.
    // Not a stream-ordered call -> does not enter / invalidate graph capture.
    cudaFuncSetAttribute(persist_kernel,
                         cudaFuncAttributeMaxDynamicSharedMemorySize, DYNSMEM);

    persist_kernel<<<NPROB, TPB, DYNSMEM>>>(xr, A, b, low, out);
}